// round 15
// baseline (speedup 1.0000x reference)
#include <cuda_runtime.h>
#include <cuda_bf16.h>
#include <cuda_fp16.h>
#include <math.h>
#include <cstdint>

// ---------------------------------------------------------------------------
// Transformer block on GB300 (compute_103-safe):
//   QKV: fp16 2-term split MMA.  Attention: fp16 2-term (K,V split).
//   FC1/FC2: plain single fp16 MMA.  fp32 accumulate everywhere.
//   B=4, T=2048, C=1024, H=16, D=64
// ---------------------------------------------------------------------------

#define Bsz   4
#define Tsz   2048
#define Csz   1024
#define Hsz   16
#define Dsz   64
#define Msz   (Bsz * Tsz)           // 8192 rows

// ---------------- scratch (device globals; no allocations allowed) ----------
__device__ float g_attn[Msz * Csz];
__device__ float g_x1  [Msz * Csz];
__device__ float g_mlp [Msz * Csz];

__device__ __half g_x_f16 [Msz * Csz];
__device__ __half g_qkv_h [Msz * 3 * Csz], g_qkv_l [Msz * 3 * Csz];
__device__ __half g_x1_h16[Msz * Csz];
__device__ __half g_h_h16 [Msz * 4 * Csz];

__device__ __half g_wqkv_h[3 * Csz * Csz], g_wqkv_l[3 * Csz * Csz];
__device__ __half g_wfc1_h[4 * Csz * Csz];
__device__ __half g_wfc2_h[Csz * 4 * Csz];

// ---------------- helpers ---------------------------------------------------
__device__ __forceinline__ uint32_t smem_u32(const void* p) {
    uint32_t a;
    asm("{ .reg .u64 t; cvta.to.shared.u64 t, %1; cvt.u32.u64 %0, t; }" : "=r"(a) : "l"(p));
    return a;
}
__device__ __forceinline__ void cp16(uint32_t dst, const void* src) {
    asm volatile("cp.async.cg.shared.global [%0], [%1], 16;\n" :: "r"(dst), "l"(src));
}
__device__ __forceinline__ void cp_commit() {
    asm volatile("cp.async.commit_group;\n" ::: "memory");
}
__device__ __forceinline__ void ldsm_x4(uint32_t* r, uint32_t addr) {
    asm volatile("ldmatrix.sync.aligned.m8n8.x4.shared.b16 {%0,%1,%2,%3}, [%4];"
                 : "=r"(r[0]), "=r"(r[1]), "=r"(r[2]), "=r"(r[3]) : "r"(addr));
}
__device__ __forceinline__ void ldsm_x4_t(uint32_t* r, uint32_t addr) {
    asm volatile("ldmatrix.sync.aligned.m8n8.x4.trans.shared.b16 {%0,%1,%2,%3}, [%4];"
                 : "=r"(r[0]), "=r"(r[1]), "=r"(r[2]), "=r"(r[3]) : "r"(addr));
}
__device__ __forceinline__ void mma16816h(float* c, const uint32_t* a, const uint32_t* b) {
    asm volatile(
        "mma.sync.aligned.m16n8k16.row.col.f32.f16.f16.f32 "
        "{%0,%1,%2,%3}, {%4,%5,%6,%7}, {%8,%9}, {%0,%1,%2,%3};"
        : "+f"(c[0]), "+f"(c[1]), "+f"(c[2]), "+f"(c[3])
        : "r"(a[0]), "r"(a[1]), "r"(a[2]), "r"(a[3]), "r"(b[0]), "r"(b[1]));
}
__device__ __forceinline__ uint32_t pack_f16(__half a, __half b) {
    return (uint32_t)__half_as_ushort(a) | ((uint32_t)__half_as_ushort(b) << 16);
}
// fast exp on the FMA pipe
__device__ __forceinline__ float fexp(float x) {
    x = fmaxf(x, -80.0f);
    float y = x * 1.4426950408889634f;
    float n = rintf(y);
    float f = y - n;
    float p = 0.0013333558f;
    p = fmaf(p, f, 0.0096181291f);
    p = fmaf(p, f, 0.0555041087f);
    p = fmaf(p, f, 0.2402265069f);
    p = fmaf(p, f, 0.6931471806f);
    p = fmaf(p, f, 1.0f);
    return __int_as_float(__float_as_int(p) + (((int)n) << 23));
}

#define TPITCH   80
#define TILE_B   (128 * TPITCH)      // 10240

// ---------------------------------------------------------------------------
// GEMM: C = Ah[M,K] @ (Bh[+Bl])[N,K]^T + bias.  NT = #B terms (1 or 2).
// 128x128, BK=32, 3-stage cp.async, 256 threads.
// EPI=0: fp32 out. EPI=1: exact GELU -> fp16. EPI=2: fp16 hi+lo out.
// ---------------------------------------------------------------------------
#define FC_SMEM_MAX (3 * 3 * TILE_B)   // 92160 (2-term case)

template <int EPI, int NT>
__global__ __launch_bounds__(256, 1) void fc_gemm(
    const __half* __restrict__ Ah,
    const __half* __restrict__ Bh, const __half* __restrict__ Bl,
    const float* __restrict__ bias,
    float* __restrict__ outF, __half* __restrict__ outH, __half* __restrict__ outL,
    int M, int N, int K)
{
    const int NTILES  = 1 + NT;               // A + B terms
    const int STAGE_B = NTILES * TILE_B;

    extern __shared__ __align__(16) char dynsm[];
    const uint32_t sbase = smem_u32(dynsm);

    const int tid  = threadIdx.x;
    const int lane = tid & 31;
    const int wid  = tid >> 5;
    const int wm   = (wid & 1) * 64;
    const int wn   = (wid >> 1) * 32;
    const int bm   = blockIdx.y * 128;
    const int bn   = blockIdx.x * 128;

    const __half* tsrc[3] = {
        Ah + (size_t)bm * K, Bh + (size_t)bn * K,
        NT == 2 ? Bl + (size_t)bn * K : Bh + (size_t)bn * K };

    auto prefetch = [&](int chunk, int st) {
        const int k0 = chunk << 5;
        const uint32_t so = sbase + st * STAGE_B;
#pragma unroll
        for (int j = 0; j < 2 * NTILES; j++) {
            int cid  = tid + j * 256;
            int tile = cid >> 9;
            int w    = cid & 511;
            int r    = w >> 2;
            int c    = w & 3;
            cp16(so + tile * TILE_B + r * TPITCH + c * 16,
                 tsrc[tile] + (size_t)r * K + k0 + c * 8);
        }
        cp_commit();
    };

    float acc[4][4][4];
#pragma unroll
    for (int i = 0; i < 4; i++)
#pragma unroll
        for (int j = 0; j < 4; j++)
#pragma unroll
            for (int q = 0; q < 4; q++) acc[i][j][q] = 0.0f;

    const int a_row  = lane & 15;
    const int a_coff = (lane >> 4) * 16;
    const int b_row  = ((lane & 16) >> 1) + (lane & 7);
    const int b_coff = ((lane >> 3) & 1) * 16;

    const int NC = K >> 5;
    prefetch(0, 0);
    prefetch(1, 1);

    for (int i = 0; i < NC; i++) {
        const int st = i % 3;
        if (i + 2 < NC) {
            prefetch(i + 2, (i + 2) % 3);
            asm volatile("cp.async.wait_group 2;\n" ::: "memory");
        } else if (i + 1 < NC) {
            asm volatile("cp.async.wait_group 1;\n" ::: "memory");
        } else {
            asm volatile("cp.async.wait_group 0;\n" ::: "memory");
        }
        __syncthreads();

        const uint32_t so  = sbase + st * STAGE_B;
        const uint32_t sA  = so;
        const uint32_t sBh = so + TILE_B;
        const uint32_t sBl = so + 2 * TILE_B;

#pragma unroll
        for (int ks = 0; ks < 2; ks++) {
            const uint32_t kb = ks * 32;
            uint32_t a[4][4], bh[4][2], bl[4][2];
#pragma unroll
            for (int mi = 0; mi < 4; mi++) {
                uint32_t ro = (uint32_t)(wm + mi * 16 + a_row) * TPITCH + kb + a_coff;
                ldsm_x4(a[mi], sA + ro);
            }
#pragma unroll
            for (int p = 0; p < 2; p++) {
                uint32_t ro = (uint32_t)(wn + p * 16 + b_row) * TPITCH + kb + b_coff;
                uint32_t th[4];
                ldsm_x4(th, sBh + ro);
                bh[2 * p][0] = th[0]; bh[2 * p][1] = th[1];
                bh[2 * p + 1][0] = th[2]; bh[2 * p + 1][1] = th[3];
                if (NT == 2) {
                    uint32_t tl[4];
                    ldsm_x4(tl, sBl + ro);
                    bl[2 * p][0] = tl[0]; bl[2 * p][1] = tl[1];
                    bl[2 * p + 1][0] = tl[2]; bl[2 * p + 1][1] = tl[3];
                }
            }
#pragma unroll
            for (int mi = 0; mi < 4; mi++)
#pragma unroll
                for (int ni = 0; ni < 4; ni++) {
                    mma16816h(acc[mi][ni], a[mi], bh[ni]);
                    if (NT == 2) mma16816h(acc[mi][ni], a[mi], bl[ni]);
                }
        }
        __syncthreads();
    }

    const int g = lane >> 2, t = lane & 3;
#pragma unroll
    for (int mi = 0; mi < 4; mi++) {
#pragma unroll
        for (int ni = 0; ni < 4; ni++) {
            const int col  = bn + wn + ni * 8 + 2 * t;
            const int row0 = bm + wm + mi * 16 + g;
            const float2 b2 = *(const float2*)(bias + col);
            float v0 = acc[mi][ni][0] + b2.x;
            float v1 = acc[mi][ni][1] + b2.y;
            float v2 = acc[mi][ni][2] + b2.x;
            float v3 = acc[mi][ni][3] + b2.y;
            if (EPI == 1) {
                v0 = 0.5f * v0 * (1.0f + erff(v0 * 0.70710678118654752f));
                v1 = 0.5f * v1 * (1.0f + erff(v1 * 0.70710678118654752f));
                v2 = 0.5f * v2 * (1.0f + erff(v2 * 0.70710678118654752f));
                v3 = 0.5f * v3 * (1.0f + erff(v3 * 0.70710678118654752f));
            }
            size_t o0 = (size_t)row0 * N + col;
            size_t o1 = (size_t)(row0 + 8) * N + col;
            if (EPI == 0) {
                *(float2*)(outF + o0) = make_float2(v0, v1);
                *(float2*)(outF + o1) = make_float2(v2, v3);
            } else if (EPI == 1) {
                *(uint32_t*)(outH + o0) = pack_f16(__float2half(v0), __float2half(v1));
                *(uint32_t*)(outH + o1) = pack_f16(__float2half(v2), __float2half(v3));
            } else {
                __half h0 = __float2half(v0), h1 = __float2half(v1);
                __half h2 = __float2half(v2), h3 = __float2half(v3);
                *(uint32_t*)(outH + o0) = pack_f16(h0, h1);
                *(uint32_t*)(outH + o1) = pack_f16(h2, h3);
                *(uint32_t*)(outL + o0) = pack_f16(
                    __float2half(v0 - __half2float(h0)),
                    __float2half(v1 - __half2float(h1)));
                *(uint32_t*)(outL + o1) = pack_f16(
                    __float2half(v2 - __half2float(h2)),
                    __float2half(v3 - __half2float(h3)));
            }
        }
    }
}

// ---------------------------------------------------------------------------
// MMA flash attention (fp16 2-term, fp32 acc): S = Q(Kh+Kl), Y = P(Vh+Vl).
// Q,P plain fp16; fp32 softmax, poly exp.  (R11 form)
// ---------------------------------------------------------------------------
#define ATPITCH    144
#define ATT_TILE   (64 * ATPITCH)        // 9216
#define ATT_Q      0
#define ATT_ST0    ATT_TILE
#define ATT_STAGE  (4 * ATT_TILE)        // KH|KL|VH|VL
#define ATT_SMEM   (ATT_TILE + 2 * ATT_STAGE)   // 82944

__global__ __launch_bounds__(128, 1) void attn_mma_kernel(
    const __half* __restrict__ qkvh, const __half* __restrict__ qkvl,
    float* __restrict__ out)
{
    extern __shared__ __align__(16) char dynsm[];
    const uint32_t sb = smem_u32(dynsm);

    const int tid = threadIdx.x, lane = tid & 31, w = tid >> 5;
    const int b = blockIdx.z, h = blockIdx.y;
    const int qt = (int)(gridDim.x - 1) - (int)blockIdx.x;   // heavy tiles first
    const int row0g = b * Tsz + qt * 64;
    const size_t rs = 3 * Csz;

    // Q tile (plain fp16 = hi part)
    {
        const __half* qp = qkvh + (size_t)row0g * rs + h * Dsz;
#pragma unroll
        for (int j = 0; j < 4; j++) {
            int cid = tid + j * 128;
            int r = cid >> 3, c = cid & 7;
            cp16(sb + ATT_Q + r * ATPITCH + c * 16, qp + (size_t)r * rs + c * 8);
        }
    }
    auto load_kv = [&](int kt, int st) {
        const uint32_t so = sb + ATT_ST0 + st * ATT_STAGE;
        const size_t gr = (size_t)(b * Tsz + kt * 64) * rs;
        const __half* kh = qkvh + gr + Csz + h * Dsz;
        const __half* kl = qkvl + gr + Csz + h * Dsz;
        const __half* vh = qkvh + gr + 2 * Csz + h * Dsz;
        const __half* vl = qkvl + gr + 2 * Csz + h * Dsz;
#pragma unroll
        for (int j = 0; j < 4; j++) {
            int cid = tid + j * 128;
            int r = cid >> 3, c = cid & 7;
            uint32_t o = r * ATPITCH + c * 16;
            size_t gg = (size_t)r * rs + c * 8;
            cp16(so + o,                kh + gg);
            cp16(so + ATT_TILE + o,     kl + gg);
            cp16(so + 2 * ATT_TILE + o, vh + gg);
            cp16(so + 3 * ATT_TILE + o, vl + gg);
        }
        cp_commit();
    };
    load_kv(0, 0);   // commits Q + stage0 together

    const int g = lane >> 2, t4 = lane & 3;
    const int a_row  = lane & 15;
    const int a_coff = (lane >> 4) * 16;
    const int b_row  = ((lane & 16) >> 1) + (lane & 7);
    const int b_coff = ((lane >> 3) & 1) * 16;
    const int v_row  = ((lane >> 3) & 1) * 8 + (lane & 7);
    const int v_coff = (lane >> 4) * 16;

    float yAcc[8][4];
#pragma unroll
    for (int nf = 0; nf < 8; nf++)
#pragma unroll
        for (int q = 0; q < 4; q++) yAcc[nf][q] = 0.0f;
    float m0 = -INFINITY, m1 = -INFINITY, l0 = 0.0f, l1 = 0.0f;

    for (int kt = 0; kt <= qt; kt++) {
        const int st = kt & 1;
        if (kt + 1 <= qt) {
            load_kv(kt + 1, (kt + 1) & 1);
            asm volatile("cp.async.wait_group 1;\n" ::: "memory");
        } else {
            asm volatile("cp.async.wait_group 0;\n" ::: "memory");
        }
        __syncthreads();

        const uint32_t soKh = sb + ATT_ST0 + st * ATT_STAGE;
        const uint32_t soKl = soKh + ATT_TILE;
        const uint32_t soVh = soKh + 2 * ATT_TILE;
        const uint32_t soVl = soKh + 3 * ATT_TILE;

        // ---- S = Q (Kh + Kl) ----
        float s[8][4];
#pragma unroll
        for (int nf = 0; nf < 8; nf++)
#pragma unroll
            for (int q = 0; q < 4; q++) s[nf][q] = 0.0f;

#pragma unroll
        for (int ks = 0; ks < 4; ks++) {
            uint32_t qro = (uint32_t)(w * 16 + a_row) * ATPITCH + ks * 32 + a_coff;
            uint32_t qf[4];
            ldsm_x4(qf, sb + ATT_Q + qro);
#pragma unroll
            for (int p = 0; p < 4; p++) {
                uint32_t kro = (uint32_t)(p * 16 + b_row) * ATPITCH + ks * 32 + b_coff;
                uint32_t th[4], tl[4];
                ldsm_x4(th, soKh + kro);
                ldsm_x4(tl, soKl + kro);
                uint32_t bh0[2] = {th[0], th[1]}, bh1[2] = {th[2], th[3]};
                uint32_t bl0[2] = {tl[0], tl[1]}, bl1[2] = {tl[2], tl[3]};
                mma16816h(s[2 * p], qf, bh0);
                mma16816h(s[2 * p], qf, bl0);
                mma16816h(s[2 * p + 1], qf, bh1);
                mma16816h(s[2 * p + 1], qf, bl1);
            }
        }

        // scale + causal mask (diagonal tile only)
        const int r0l = w * 16 + g, r1l = r0l + 8;
#pragma unroll
        for (int nf = 0; nf < 8; nf++) {
            int c0 = nf * 8 + 2 * t4, c1 = c0 + 1;
            s[nf][0] *= 0.125f; s[nf][1] *= 0.125f;
            s[nf][2] *= 0.125f; s[nf][3] *= 0.125f;
            if (kt == qt) {
                if (c0 > r0l) s[nf][0] = -1e30f;
                if (c1 > r0l) s[nf][1] = -1e30f;
                if (c0 > r1l) s[nf][2] = -1e30f;
                if (c1 > r1l) s[nf][3] = -1e30f;
            }
        }

        // ---- online softmax ----
        float mx0 = -INFINITY, mx1 = -INFINITY;
#pragma unroll
        for (int nf = 0; nf < 8; nf++) {
            mx0 = fmaxf(mx0, fmaxf(s[nf][0], s[nf][1]));
            mx1 = fmaxf(mx1, fmaxf(s[nf][2], s[nf][3]));
        }
        mx0 = fmaxf(mx0, __shfl_xor_sync(0xffffffffu, mx0, 1));
        mx0 = fmaxf(mx0, __shfl_xor_sync(0xffffffffu, mx0, 2));
        mx1 = fmaxf(mx1, __shfl_xor_sync(0xffffffffu, mx1, 1));
        mx1 = fmaxf(mx1, __shfl_xor_sync(0xffffffffu, mx1, 2));
        const float mn0 = fmaxf(m0, mx0), mn1 = fmaxf(m1, mx1);
        const float sc0 = fexp(m0 - mn0), sc1 = fexp(m1 - mn1);
        m0 = mn0; m1 = mn1;

        float sum0 = 0.0f, sum1 = 0.0f;
#pragma unroll
        for (int nf = 0; nf < 8; nf++) {
            s[nf][0] = fexp(s[nf][0] - mn0);
            s[nf][1] = fexp(s[nf][1] - mn0);
            s[nf][2] = fexp(s[nf][2] - mn1);
            s[nf][3] = fexp(s[nf][3] - mn1);
            sum0 += s[nf][0] + s[nf][1];
            sum1 += s[nf][2] + s[nf][3];
        }
        sum0 += __shfl_xor_sync(0xffffffffu, sum0, 1);
        sum0 += __shfl_xor_sync(0xffffffffu, sum0, 2);
        sum1 += __shfl_xor_sync(0xffffffffu, sum1, 1);
        sum1 += __shfl_xor_sync(0xffffffffu, sum1, 2);
        l0 = l0 * sc0 + sum0;
        l1 = l1 * sc1 + sum1;
#pragma unroll
        for (int nf = 0; nf < 8; nf++) {
            yAcc[nf][0] *= sc0; yAcc[nf][1] *= sc0;
            yAcc[nf][2] *= sc1; yAcc[nf][3] *= sc1;
        }

        // ---- P -> plain fp16 A-frags ----
        uint32_t pH[4][4];
#pragma unroll
        for (int ks = 0; ks < 4; ks++) {
#pragma unroll
            for (int hf = 0; hf < 2; hf++) {
                int j = 2 * ks + hf;
                pH[ks][2 * hf]     = pack_f16(__float2half(s[j][0]), __float2half(s[j][1]));
                pH[ks][2 * hf + 1] = pack_f16(__float2half(s[j][2]), __float2half(s[j][3]));
            }
        }

        // ---- Y += P (Vh + Vl) ----
#pragma unroll
        for (int ks = 0; ks < 4; ks++) {
#pragma unroll
            for (int np = 0; np < 4; np++) {
                uint32_t vo = (uint32_t)(ks * 16 + v_row) * ATPITCH + np * 32 + v_coff;
                uint32_t tv[4], tw[4];
                ldsm_x4_t(tv, soVh + vo);
                ldsm_x4_t(tw, soVl + vo);
                uint32_t bh0[2] = {tv[0], tv[1]}, bh1[2] = {tv[2], tv[3]};
                uint32_t bl0[2] = {tw[0], tw[1]}, bl1[2] = {tw[2], tw[3]};
                mma16816h(yAcc[2 * np], pH[ks], bh0);
                mma16816h(yAcc[2 * np], pH[ks], bl0);
                mma16816h(yAcc[2 * np + 1], pH[ks], bh1);
                mma16816h(yAcc[2 * np + 1], pH[ks], bl1);
            }
        }
        __syncthreads();
    }

    const float i0 = 1.0f / l0, i1 = 1.0f / l1;
    float* o0 = out + (size_t)(row0g + w * 16 + g) * Csz + h * Dsz;
    float* o1 = o0 + 8 * Csz;
#pragma unroll
    for (int nf = 0; nf < 8; nf++) {
        int c = nf * 8 + 2 * t4;
        *(float2*)(o0 + c) = make_float2(yAcc[nf][0] * i0, yAcc[nf][1] * i0);
        *(float2*)(o1 + c) = make_float2(yAcc[nf][2] * i1, yAcc[nf][3] * i1);
    }
}

// ---------------------------------------------------------------------------
// fp32 -> fp16 (x for QKV GEMM A operand)
// ---------------------------------------------------------------------------
__global__ __launch_bounds__(256) void tofp16_kernel(
    const float* __restrict__ in, __half* __restrict__ o, int n4)
{
    int i = blockIdx.x * blockDim.x + threadIdx.x;
    if (i >= n4) return;
    float4 v = *(const float4*)(in + i * 4);
    *(uint2*)(o + i * 4) = make_uint2(
        pack_f16(__float2half(v.x), __float2half(v.y)),
        pack_f16(__float2half(v.z), __float2half(v.w)));
}

// ---------------------------------------------------------------------------
// W [K,N] fp32 -> Wt [N,K] fp16 hi (+ optional lo) (tiled transpose)
// ---------------------------------------------------------------------------
__global__ __launch_bounds__(256) void wsplit_t_f16_kernel(
    const float* __restrict__ W, __half* __restrict__ hi,
    __half* __restrict__ lo, int K, int N)
{
    __shared__ float t[32][33];
    int k0 = blockIdx.y * 32, n0 = blockIdx.x * 32;
    int tx = threadIdx.x & 31, ty = threadIdx.x >> 5;
#pragma unroll
    for (int i = 0; i < 32; i += 8)
        t[ty + i][tx] = W[(size_t)(k0 + ty + i) * N + n0 + tx];
    __syncthreads();
#pragma unroll
    for (int i = 0; i < 32; i += 8) {
        float v = t[tx][ty + i];
        __half h = __float2half(v);
        size_t off = (size_t)(n0 + ty + i) * K + k0 + tx;
        hi[off] = h;
        if (lo) lo[off] = __float2half(v - __half2float(h));
    }
}

// ---------------------------------------------------------------------------
// Residual add + LayerNorm (+ optional fp16 emit)
// ---------------------------------------------------------------------------
__global__ __launch_bounds__(256) void add_ln_kernel(
    const float* __restrict__ a, const float* __restrict__ bsrc,
    const float* __restrict__ g, const float* __restrict__ beta,
    float* __restrict__ out, __half* __restrict__ oh16)
{
    __shared__ float red[256];
    __shared__ float s_mu, s_rstd;

    const int row = blockIdx.x;
    const int tid = threadIdx.x;
    const float* pa = a + (size_t)row * Csz;
    const float* pb = bsrc + (size_t)row * Csz;

    float v[4];
#pragma unroll
    for (int i = 0; i < 4; i++) {
        int c = tid + i * 256;
        v[i] = pa[c] + pb[c];
    }

    float s = v[0] + v[1] + v[2] + v[3];
    red[tid] = s;
    __syncthreads();
    for (int off = 128; off > 0; off >>= 1) {
        if (tid < off) red[tid] += red[tid + off];
        __syncthreads();
    }
    if (tid == 0) s_mu = red[0] * (1.0f / Csz);
    __syncthreads();
    const float mu = s_mu;

    float d2 = 0.0f;
#pragma unroll
    for (int i = 0; i < 4; i++) {
        float d = v[i] - mu;
        d2 = fmaf(d, d, d2);
    }
    __syncthreads();
    red[tid] = d2;
    __syncthreads();
    for (int off = 128; off > 0; off >>= 1) {
        if (tid < off) red[tid] += red[tid + off];
        __syncthreads();
    }
    if (tid == 0) s_rstd = rsqrtf(red[0] * (1.0f / Csz) + 1e-5f);
    __syncthreads();
    const float rstd = s_rstd;

#pragma unroll
    for (int i = 0; i < 4; i++) {
        int c = tid + i * 256;
        float o = (v[i] - mu) * rstd * g[c] + beta[c];
        out[(size_t)row * Csz + c] = o;
        if (oh16) oh16[(size_t)row * Csz + c] = __float2half(o);
    }
}

// ---------------------------------------------------------------------------
// Launch
// ---------------------------------------------------------------------------
extern "C" void kernel_launch(void* const* d_in, const int* in_sizes, int n_in,
                              void* d_out, int out_size)
{
    const float* x     = (const float*)d_in[0];
    const float* w_qkv = (const float*)d_in[1];
    const float* b_qkv = (const float*)d_in[2];
    const float* ln1_g = (const float*)d_in[3];
    const float* ln1_b = (const float*)d_in[4];
    const float* w_fc1 = (const float*)d_in[5];
    const float* b_fc1 = (const float*)d_in[6];
    const float* w_fc2 = (const float*)d_in[7];
    const float* b_fc2 = (const float*)d_in[8];
    const float* ln2_g = (const float*)d_in[9];
    const float* ln2_b = (const float*)d_in[10];
    float* out = (float*)d_out;

    float *attn, *x1, *mlp;
    __half *x16, *qkvh, *qkvl, *x1h16, *h16;
    __half *wqh, *wql, *w1h, *w2h;
    cudaGetSymbolAddress((void**)&attn, g_attn);
    cudaGetSymbolAddress((void**)&x1,   g_x1);
    cudaGetSymbolAddress((void**)&mlp,  g_mlp);
    cudaGetSymbolAddress((void**)&x16,  g_x_f16);
    cudaGetSymbolAddress((void**)&qkvh, g_qkv_h); cudaGetSymbolAddress((void**)&qkvl, g_qkv_l);
    cudaGetSymbolAddress((void**)&x1h16, g_x1_h16);
    cudaGetSymbolAddress((void**)&h16,   g_h_h16);
    cudaGetSymbolAddress((void**)&wqh, g_wqkv_h); cudaGetSymbolAddress((void**)&wql, g_wqkv_l);
    cudaGetSymbolAddress((void**)&w1h, g_wfc1_h);
    cudaGetSymbolAddress((void**)&w2h, g_wfc2_h);

    cudaFuncSetAttribute(fc_gemm<2, 2>, cudaFuncAttributeMaxDynamicSharedMemorySize, FC_SMEM_MAX);
    cudaFuncSetAttribute(fc_gemm<1, 1>, cudaFuncAttributeMaxDynamicSharedMemorySize, FC_SMEM_MAX);
    cudaFuncSetAttribute(fc_gemm<0, 1>, cudaFuncAttributeMaxDynamicSharedMemorySize, FC_SMEM_MAX);
    cudaFuncSetAttribute(attn_mma_kernel, cudaFuncAttributeMaxDynamicSharedMemorySize, ATT_SMEM);

    // Prep: x -> fp16; transpose(+split) weights
    tofp16_kernel<<<(Msz * Csz / 4 + 255) / 256, 256>>>(x, x16, Msz * Csz / 4);
    wsplit_t_f16_kernel<<<dim3(3 * Csz / 32, Csz / 32), 256>>>(w_qkv, wqh, wql, Csz, 3 * Csz);
    wsplit_t_f16_kernel<<<dim3(4 * Csz / 32, Csz / 32), 256>>>(w_fc1, w1h, nullptr, Csz, 4 * Csz);
    wsplit_t_f16_kernel<<<dim3(Csz / 32, 4 * Csz / 32), 256>>>(w_fc2, w2h, nullptr, 4 * Csz, Csz);

    // 1. qkv = x @ Wqkv + b  (2-term) -> fp16 hi + lo
    fc_gemm<2, 2><<<dim3(3 * Csz / 128, Msz / 128), 256, 3 * 3 * TILE_B>>>(
        x16, wqh, wql, b_qkv, nullptr, qkvh, qkvl, Msz, 3 * Csz, Csz);

    // 2. attention (fp16 2-term MMA)
    attn_mma_kernel<<<dim3(Tsz / 64, Hsz, Bsz), 128, ATT_SMEM>>>(qkvh, qkvl, attn);

    // 3. x1 = LN1(x + attn)  (+ fp16 emit)
    add_ln_kernel<<<Msz, 256>>>(x, attn, ln1_g, ln1_b, x1, x1h16);

    // 4. h = gelu(x1 @ W1 + b1)  (1-term) -> fp16
    fc_gemm<1, 1><<<dim3(4 * Csz / 128, Msz / 128), 256, 3 * 2 * TILE_B>>>(
        x1h16, w1h, nullptr, b_fc1, nullptr, h16, nullptr, Msz, 4 * Csz, Csz);

    // 5. mlp = h @ W2 + b2  (1-term) -> fp32
    fc_gemm<0, 1><<<dim3(Csz / 128, Msz / 128), 256, 3 * 2 * TILE_B>>>(
        h16, w2h, nullptr, b_fc2, mlp, nullptr, nullptr, Msz, Csz, 4 * Csz);

    // 6. out = LN2(x1 + mlp)
    add_ln_kernel<<<Msz, 256>>>(x1, mlp, ln2_g, ln2_b, out, nullptr);
}

// round 16
// speedup vs baseline: 1.7567x; 1.7567x over previous
#include <cuda_runtime.h>
#include <cuda_bf16.h>
#include <cuda_fp16.h>
#include <math.h>
#include <cstdint>

// ---------------------------------------------------------------------------
// Transformer block on GB300 (compute_103-safe):
//   QKV: fp16 2-term split MMA.  Attention: fp16 2-term (K,V split).
//   FC1/FC2: plain single fp16 MMA.  BK=64 stages (halved sync overhead).
//   B=4, T=2048, C=1024, H=16, D=64
// ---------------------------------------------------------------------------

#define Bsz   4
#define Tsz   2048
#define Csz   1024
#define Hsz   16
#define Dsz   64
#define Msz   (Bsz * Tsz)           // 8192 rows

// ---------------- scratch (device globals; no allocations allowed) ----------
__device__ float g_attn[Msz * Csz];
__device__ float g_x1  [Msz * Csz];
__device__ float g_mlp [Msz * Csz];

__device__ __half g_x_f16 [Msz * Csz];
__device__ __half g_qkv_h [Msz * 3 * Csz], g_qkv_l [Msz * 3 * Csz];
__device__ __half g_x1_h16[Msz * Csz];
__device__ __half g_h_h16 [Msz * 4 * Csz];

__device__ __half g_wqkv_h[3 * Csz * Csz], g_wqkv_l[3 * Csz * Csz];
__device__ __half g_wfc1_h[4 * Csz * Csz];
__device__ __half g_wfc2_h[Csz * 4 * Csz];

// ---------------- helpers ---------------------------------------------------
__device__ __forceinline__ uint32_t smem_u32(const void* p) {
    uint32_t a;
    asm("{ .reg .u64 t; cvta.to.shared.u64 t, %1; cvt.u32.u64 %0, t; }" : "=r"(a) : "l"(p));
    return a;
}
__device__ __forceinline__ void cp16(uint32_t dst, const void* src) {
    asm volatile("cp.async.cg.shared.global [%0], [%1], 16;\n" :: "r"(dst), "l"(src));
}
__device__ __forceinline__ void cp_commit() {
    asm volatile("cp.async.commit_group;\n" ::: "memory");
}
__device__ __forceinline__ void ldsm_x4(uint32_t* r, uint32_t addr) {
    asm volatile("ldmatrix.sync.aligned.m8n8.x4.shared.b16 {%0,%1,%2,%3}, [%4];"
                 : "=r"(r[0]), "=r"(r[1]), "=r"(r[2]), "=r"(r[3]) : "r"(addr));
}
__device__ __forceinline__ void ldsm_x4_t(uint32_t* r, uint32_t addr) {
    asm volatile("ldmatrix.sync.aligned.m8n8.x4.trans.shared.b16 {%0,%1,%2,%3}, [%4];"
                 : "=r"(r[0]), "=r"(r[1]), "=r"(r[2]), "=r"(r[3]) : "r"(addr));
}
__device__ __forceinline__ void mma16816h(float* c, const uint32_t* a, const uint32_t* b) {
    asm volatile(
        "mma.sync.aligned.m16n8k16.row.col.f32.f16.f16.f32 "
        "{%0,%1,%2,%3}, {%4,%5,%6,%7}, {%8,%9}, {%0,%1,%2,%3};"
        : "+f"(c[0]), "+f"(c[1]), "+f"(c[2]), "+f"(c[3])
        : "r"(a[0]), "r"(a[1]), "r"(a[2]), "r"(a[3]), "r"(b[0]), "r"(b[1]));
}
__device__ __forceinline__ uint32_t pack_f16(__half a, __half b) {
    return (uint32_t)__half_as_ushort(a) | ((uint32_t)__half_as_ushort(b) << 16);
}
// fast exp on the FMA pipe
__device__ __forceinline__ float fexp(float x) {
    x = fmaxf(x, -80.0f);
    float y = x * 1.4426950408889634f;
    float n = rintf(y);
    float f = y - n;
    float p = 0.0013333558f;
    p = fmaf(p, f, 0.0096181291f);
    p = fmaf(p, f, 0.0555041087f);
    p = fmaf(p, f, 0.2402265069f);
    p = fmaf(p, f, 0.6931471806f);
    p = fmaf(p, f, 1.0f);
    return __int_as_float(__float_as_int(p) + (((int)n) << 23));
}

// ---------------------------------------------------------------------------
// GEMM: C = Ah[M,K] @ (Bh[+Bl])[N,K]^T + bias.  NT = #B terms (1 or 2).
// 128x128 tile, BK=64 (pitch 144B, conflict-free), 2-stage cp.async, 256 thr.
// EPI=0: fp32 out. EPI=1: exact GELU -> fp16. EPI=2: fp16 hi+lo out.
// ---------------------------------------------------------------------------
#define GPITCH    144                 // 128B data + 16B pad
#define GTILE_B   (128 * GPITCH)      // 18432
#define G_SMEM_MAX (2 * 3 * GTILE_B)  // 110592 (2-term QKV case)

template <int EPI, int NT>
__global__ __launch_bounds__(256, 1) void fc_gemm(
    const __half* __restrict__ Ah,
    const __half* __restrict__ Bh, const __half* __restrict__ Bl,
    const float* __restrict__ bias,
    float* __restrict__ outF, __half* __restrict__ outH, __half* __restrict__ outL,
    int M, int N, int K)
{
    const int NTILES  = 1 + NT;               // A + B terms
    const int STAGE_B = NTILES * GTILE_B;

    extern __shared__ __align__(16) char dynsm[];
    const uint32_t sbase = smem_u32(dynsm);

    const int tid  = threadIdx.x;
    const int lane = tid & 31;
    const int wid  = tid >> 5;
    const int wm   = (wid & 1) * 64;
    const int wn   = (wid >> 1) * 32;
    const int bm   = blockIdx.y * 128;
    const int bn   = blockIdx.x * 128;

    const __half* tsrc[3] = {
        Ah + (size_t)bm * K, Bh + (size_t)bn * K,
        NT == 2 ? Bl + (size_t)bn * K : Bh + (size_t)bn * K };

    // one BK=64 chunk: per tile 128 rows x 64 halves = 1024 x 16B
    auto prefetch = [&](int chunk, int st) {
        const int k0 = chunk << 6;
        const uint32_t so = sbase + st * STAGE_B;
#pragma unroll
        for (int j = 0; j < 4 * NTILES; j++) {
            int cid  = tid + j * 256;          // 0..(1024*NTILES-1)
            int tile = cid >> 10;
            int w    = cid & 1023;
            int r    = w >> 3;                 // 0..127
            int c    = w & 7;                  // 16B chunk
            cp16(so + tile * GTILE_B + r * GPITCH + c * 16,
                 tsrc[tile] + (size_t)r * K + k0 + c * 8);
        }
        cp_commit();
    };

    float acc[4][4][4];
#pragma unroll
    for (int i = 0; i < 4; i++)
#pragma unroll
        for (int j = 0; j < 4; j++)
#pragma unroll
            for (int q = 0; q < 4; q++) acc[i][j][q] = 0.0f;

    const int a_row  = lane & 15;
    const int a_coff = (lane >> 4) * 16;
    const int b_row  = ((lane & 16) >> 1) + (lane & 7);
    const int b_coff = ((lane >> 3) & 1) * 16;

    const int NC = K >> 6;
    prefetch(0, 0);

    for (int i = 0; i < NC; i++) {
        const int st = i & 1;
        if (i + 1 < NC) {
            prefetch(i + 1, (i + 1) & 1);
            asm volatile("cp.async.wait_group 1;\n" ::: "memory");
        } else {
            asm volatile("cp.async.wait_group 0;\n" ::: "memory");
        }
        __syncthreads();

        const uint32_t so  = sbase + st * STAGE_B;
        const uint32_t sA  = so;
        const uint32_t sBh = so + GTILE_B;
        const uint32_t sBl = so + 2 * GTILE_B;

#pragma unroll
        for (int ks = 0; ks < 4; ks++) {
            const uint32_t kb = ks * 32;       // byte offset within 128B row
            uint32_t a[4][4], bh[4][2], bl[4][2];
#pragma unroll
            for (int mi = 0; mi < 4; mi++) {
                uint32_t ro = (uint32_t)(wm + mi * 16 + a_row) * GPITCH + kb + a_coff;
                ldsm_x4(a[mi], sA + ro);
            }
#pragma unroll
            for (int p = 0; p < 2; p++) {
                uint32_t ro = (uint32_t)(wn + p * 16 + b_row) * GPITCH + kb + b_coff;
                uint32_t th[4];
                ldsm_x4(th, sBh + ro);
                bh[2 * p][0] = th[0]; bh[2 * p][1] = th[1];
                bh[2 * p + 1][0] = th[2]; bh[2 * p + 1][1] = th[3];
                if (NT == 2) {
                    uint32_t tl[4];
                    ldsm_x4(tl, sBl + ro);
                    bl[2 * p][0] = tl[0]; bl[2 * p][1] = tl[1];
                    bl[2 * p + 1][0] = tl[2]; bl[2 * p + 1][1] = tl[3];
                }
            }
#pragma unroll
            for (int mi = 0; mi < 4; mi++)
#pragma unroll
                for (int ni = 0; ni < 4; ni++) {
                    mma16816h(acc[mi][ni], a[mi], bh[ni]);
                    if (NT == 2) mma16816h(acc[mi][ni], a[mi], bl[ni]);
                }
        }
        __syncthreads();
    }

    const int g = lane >> 2, t = lane & 3;
#pragma unroll
    for (int mi = 0; mi < 4; mi++) {
#pragma unroll
        for (int ni = 0; ni < 4; ni++) {
            const int col  = bn + wn + ni * 8 + 2 * t;
            const int row0 = bm + wm + mi * 16 + g;
            const float2 b2 = *(const float2*)(bias + col);
            float v0 = acc[mi][ni][0] + b2.x;
            float v1 = acc[mi][ni][1] + b2.y;
            float v2 = acc[mi][ni][2] + b2.x;
            float v3 = acc[mi][ni][3] + b2.y;
            if (EPI == 1) {
                v0 = 0.5f * v0 * (1.0f + erff(v0 * 0.70710678118654752f));
                v1 = 0.5f * v1 * (1.0f + erff(v1 * 0.70710678118654752f));
                v2 = 0.5f * v2 * (1.0f + erff(v2 * 0.70710678118654752f));
                v3 = 0.5f * v3 * (1.0f + erff(v3 * 0.70710678118654752f));
            }
            size_t o0 = (size_t)row0 * N + col;
            size_t o1 = (size_t)(row0 + 8) * N + col;
            if (EPI == 0) {
                *(float2*)(outF + o0) = make_float2(v0, v1);
                *(float2*)(outF + o1) = make_float2(v2, v3);
            } else if (EPI == 1) {
                *(uint32_t*)(outH + o0) = pack_f16(__float2half(v0), __float2half(v1));
                *(uint32_t*)(outH + o1) = pack_f16(__float2half(v2), __float2half(v3));
            } else {
                __half h0 = __float2half(v0), h1 = __float2half(v1);
                __half h2 = __float2half(v2), h3 = __float2half(v3);
                *(uint32_t*)(outH + o0) = pack_f16(h0, h1);
                *(uint32_t*)(outH + o1) = pack_f16(h2, h3);
                *(uint32_t*)(outL + o0) = pack_f16(
                    __float2half(v0 - __half2float(h0)),
                    __float2half(v1 - __half2float(h1)));
                *(uint32_t*)(outL + o1) = pack_f16(
                    __float2half(v2 - __half2float(h2)),
                    __float2half(v3 - __half2float(h3)));
            }
        }
    }
}

// ---------------------------------------------------------------------------
// MMA flash attention (fp16 2-term, fp32 acc): S = Q(Kh+Kl), Y = P(Vh+Vl).
// Q,P plain fp16; fp32 softmax, poly exp.  (R11 form, unchanged)
// ---------------------------------------------------------------------------
#define ATPITCH    144
#define ATT_TILE   (64 * ATPITCH)        // 9216
#define ATT_Q      0
#define ATT_ST0    ATT_TILE
#define ATT_STAGE  (4 * ATT_TILE)        // KH|KL|VH|VL
#define ATT_SMEM   (ATT_TILE + 2 * ATT_STAGE)   // 82944

__global__ __launch_bounds__(128, 1) void attn_mma_kernel(
    const __half* __restrict__ qkvh, const __half* __restrict__ qkvl,
    float* __restrict__ out)
{
    extern __shared__ __align__(16) char dynsm[];
    const uint32_t sb = smem_u32(dynsm);

    const int tid = threadIdx.x, lane = tid & 31, w = tid >> 5;
    const int b = blockIdx.z, h = blockIdx.y;
    const int qt = (int)(gridDim.x - 1) - (int)blockIdx.x;   // heavy tiles first
    const int row0g = b * Tsz + qt * 64;
    const size_t rs = 3 * Csz;

    {
        const __half* qp = qkvh + (size_t)row0g * rs + h * Dsz;
#pragma unroll
        for (int j = 0; j < 4; j++) {
            int cid = tid + j * 128;
            int r = cid >> 3, c = cid & 7;
            cp16(sb + ATT_Q + r * ATPITCH + c * 16, qp + (size_t)r * rs + c * 8);
        }
    }
    auto load_kv = [&](int kt, int st) {
        const uint32_t so = sb + ATT_ST0 + st * ATT_STAGE;
        const size_t gr = (size_t)(b * Tsz + kt * 64) * rs;
        const __half* kh = qkvh + gr + Csz + h * Dsz;
        const __half* kl = qkvl + gr + Csz + h * Dsz;
        const __half* vh = qkvh + gr + 2 * Csz + h * Dsz;
        const __half* vl = qkvl + gr + 2 * Csz + h * Dsz;
#pragma unroll
        for (int j = 0; j < 4; j++) {
            int cid = tid + j * 128;
            int r = cid >> 3, c = cid & 7;
            uint32_t o = r * ATPITCH + c * 16;
            size_t gg = (size_t)r * rs + c * 8;
            cp16(so + o,                kh + gg);
            cp16(so + ATT_TILE + o,     kl + gg);
            cp16(so + 2 * ATT_TILE + o, vh + gg);
            cp16(so + 3 * ATT_TILE + o, vl + gg);
        }
        cp_commit();
    };
    load_kv(0, 0);

    const int g = lane >> 2, t4 = lane & 3;
    const int a_row  = lane & 15;
    const int a_coff = (lane >> 4) * 16;
    const int b_row  = ((lane & 16) >> 1) + (lane & 7);
    const int b_coff = ((lane >> 3) & 1) * 16;
    const int v_row  = ((lane >> 3) & 1) * 8 + (lane & 7);
    const int v_coff = (lane >> 4) * 16;

    float yAcc[8][4];
#pragma unroll
    for (int nf = 0; nf < 8; nf++)
#pragma unroll
        for (int q = 0; q < 4; q++) yAcc[nf][q] = 0.0f;
    float m0 = -INFINITY, m1 = -INFINITY, l0 = 0.0f, l1 = 0.0f;

    for (int kt = 0; kt <= qt; kt++) {
        const int st = kt & 1;
        if (kt + 1 <= qt) {
            load_kv(kt + 1, (kt + 1) & 1);
            asm volatile("cp.async.wait_group 1;\n" ::: "memory");
        } else {
            asm volatile("cp.async.wait_group 0;\n" ::: "memory");
        }
        __syncthreads();

        const uint32_t soKh = sb + ATT_ST0 + st * ATT_STAGE;
        const uint32_t soKl = soKh + ATT_TILE;
        const uint32_t soVh = soKh + 2 * ATT_TILE;
        const uint32_t soVl = soKh + 3 * ATT_TILE;

        // ---- S = Q (Kh + Kl) ----
        float s[8][4];
#pragma unroll
        for (int nf = 0; nf < 8; nf++)
#pragma unroll
            for (int q = 0; q < 4; q++) s[nf][q] = 0.0f;

#pragma unroll
        for (int ks = 0; ks < 4; ks++) {
            uint32_t qro = (uint32_t)(w * 16 + a_row) * ATPITCH + ks * 32 + a_coff;
            uint32_t qf[4];
            ldsm_x4(qf, sb + ATT_Q + qro);
#pragma unroll
            for (int p = 0; p < 4; p++) {
                uint32_t kro = (uint32_t)(p * 16 + b_row) * ATPITCH + ks * 32 + b_coff;
                uint32_t th[4], tl[4];
                ldsm_x4(th, soKh + kro);
                ldsm_x4(tl, soKl + kro);
                uint32_t bh0[2] = {th[0], th[1]}, bh1[2] = {th[2], th[3]};
                uint32_t bl0[2] = {tl[0], tl[1]}, bl1[2] = {tl[2], tl[3]};
                mma16816h(s[2 * p], qf, bh0);
                mma16816h(s[2 * p], qf, bl0);
                mma16816h(s[2 * p + 1], qf, bh1);
                mma16816h(s[2 * p + 1], qf, bl1);
            }
        }

        // scale + causal mask (diagonal tile only)
        const int r0l = w * 16 + g, r1l = r0l + 8;
#pragma unroll
        for (int nf = 0; nf < 8; nf++) {
            int c0 = nf * 8 + 2 * t4, c1 = c0 + 1;
            s[nf][0] *= 0.125f; s[nf][1] *= 0.125f;
            s[nf][2] *= 0.125f; s[nf][3] *= 0.125f;
            if (kt == qt) {
                if (c0 > r0l) s[nf][0] = -1e30f;
                if (c1 > r0l) s[nf][1] = -1e30f;
                if (c0 > r1l) s[nf][2] = -1e30f;
                if (c1 > r1l) s[nf][3] = -1e30f;
            }
        }

        // ---- online softmax ----
        float mx0 = -INFINITY, mx1 = -INFINITY;
#pragma unroll
        for (int nf = 0; nf < 8; nf++) {
            mx0 = fmaxf(mx0, fmaxf(s[nf][0], s[nf][1]));
            mx1 = fmaxf(mx1, fmaxf(s[nf][2], s[nf][3]));
        }
        mx0 = fmaxf(mx0, __shfl_xor_sync(0xffffffffu, mx0, 1));
        mx0 = fmaxf(mx0, __shfl_xor_sync(0xffffffffu, mx0, 2));
        mx1 = fmaxf(mx1, __shfl_xor_sync(0xffffffffu, mx1, 1));
        mx1 = fmaxf(mx1, __shfl_xor_sync(0xffffffffu, mx1, 2));
        const float mn0 = fmaxf(m0, mx0), mn1 = fmaxf(m1, mx1);
        const float sc0 = fexp(m0 - mn0), sc1 = fexp(m1 - mn1);
        m0 = mn0; m1 = mn1;

        float sum0 = 0.0f, sum1 = 0.0f;
#pragma unroll
        for (int nf = 0; nf < 8; nf++) {
            s[nf][0] = fexp(s[nf][0] - mn0);
            s[nf][1] = fexp(s[nf][1] - mn0);
            s[nf][2] = fexp(s[nf][2] - mn1);
            s[nf][3] = fexp(s[nf][3] - mn1);
            sum0 += s[nf][0] + s[nf][1];
            sum1 += s[nf][2] + s[nf][3];
        }
        sum0 += __shfl_xor_sync(0xffffffffu, sum0, 1);
        sum0 += __shfl_xor_sync(0xffffffffu, sum0, 2);
        sum1 += __shfl_xor_sync(0xffffffffu, sum1, 1);
        sum1 += __shfl_xor_sync(0xffffffffu, sum1, 2);
        l0 = l0 * sc0 + sum0;
        l1 = l1 * sc1 + sum1;
#pragma unroll
        for (int nf = 0; nf < 8; nf++) {
            yAcc[nf][0] *= sc0; yAcc[nf][1] *= sc0;
            yAcc[nf][2] *= sc1; yAcc[nf][3] *= sc1;
        }

        // ---- P -> plain fp16 A-frags ----
        uint32_t pH[4][4];
#pragma unroll
        for (int ks = 0; ks < 4; ks++) {
#pragma unroll
            for (int hf = 0; hf < 2; hf++) {
                int j = 2 * ks + hf;
                pH[ks][2 * hf]     = pack_f16(__float2half(s[j][0]), __float2half(s[j][1]));
                pH[ks][2 * hf + 1] = pack_f16(__float2half(s[j][2]), __float2half(s[j][3]));
            }
        }

        // ---- Y += P (Vh + Vl) ----
#pragma unroll
        for (int ks = 0; ks < 4; ks++) {
#pragma unroll
            for (int np = 0; np < 4; np++) {
                uint32_t vo = (uint32_t)(ks * 16 + v_row) * ATPITCH + np * 32 + v_coff;
                uint32_t tv[4], tw[4];
                ldsm_x4_t(tv, soVh + vo);
                ldsm_x4_t(tw, soVl + vo);
                uint32_t bh0[2] = {tv[0], tv[1]}, bh1[2] = {tv[2], tv[3]};
                uint32_t bl0[2] = {tw[0], tw[1]}, bl1[2] = {tw[2], tw[3]};
                mma16816h(yAcc[2 * np], pH[ks], bh0);
                mma16816h(yAcc[2 * np], pH[ks], bl0);
                mma16816h(yAcc[2 * np + 1], pH[ks], bh1);
                mma16816h(yAcc[2 * np + 1], pH[ks], bl1);
            }
        }
        __syncthreads();
    }

    const float i0 = 1.0f / l0, i1 = 1.0f / l1;
    float* o0 = out + (size_t)(row0g + w * 16 + g) * Csz + h * Dsz;
    float* o1 = o0 + 8 * Csz;
#pragma unroll
    for (int nf = 0; nf < 8; nf++) {
        int c = nf * 8 + 2 * t4;
        *(float2*)(o0 + c) = make_float2(yAcc[nf][0] * i0, yAcc[nf][1] * i0);
        *(float2*)(o1 + c) = make_float2(yAcc[nf][2] * i1, yAcc[nf][3] * i1);
    }
}

// ---------------------------------------------------------------------------
// fp32 -> fp16 (x for QKV GEMM A operand)
// ---------------------------------------------------------------------------
__global__ __launch_bounds__(256) void tofp16_kernel(
    const float* __restrict__ in, __half* __restrict__ o, int n4)
{
    int i = blockIdx.x * blockDim.x + threadIdx.x;
    if (i >= n4) return;
    float4 v = *(const float4*)(in + i * 4);
    *(uint2*)(o + i * 4) = make_uint2(
        pack_f16(__float2half(v.x), __float2half(v.y)),
        pack_f16(__float2half(v.z), __float2half(v.w)));
}

// ---------------------------------------------------------------------------
// W [K,N] fp32 -> Wt [N,K] fp16 hi (+ optional lo) (tiled transpose)
// ---------------------------------------------------------------------------
__global__ __launch_bounds__(256) void wsplit_t_f16_kernel(
    const float* __restrict__ W, __half* __restrict__ hi,
    __half* __restrict__ lo, int K, int N)
{
    __shared__ float t[32][33];
    int k0 = blockIdx.y * 32, n0 = blockIdx.x * 32;
    int tx = threadIdx.x & 31, ty = threadIdx.x >> 5;
#pragma unroll
    for (int i = 0; i < 32; i += 8)
        t[ty + i][tx] = W[(size_t)(k0 + ty + i) * N + n0 + tx];
    __syncthreads();
#pragma unroll
    for (int i = 0; i < 32; i += 8) {
        float v = t[tx][ty + i];
        __half h = __float2half(v);
        size_t off = (size_t)(n0 + ty + i) * K + k0 + tx;
        hi[off] = h;
        if (lo) lo[off] = __float2half(v - __half2float(h));
    }
}

// ---------------------------------------------------------------------------
// Residual add + LayerNorm (+ optional fp16 emit)
// ---------------------------------------------------------------------------
__global__ __launch_bounds__(256) void add_ln_kernel(
    const float* __restrict__ a, const float* __restrict__ bsrc,
    const float* __restrict__ g, const float* __restrict__ beta,
    float* __restrict__ out, __half* __restrict__ oh16)
{
    __shared__ float red[256];
    __shared__ float s_mu, s_rstd;

    const int row = blockIdx.x;
    const int tid = threadIdx.x;
    const float* pa = a + (size_t)row * Csz;
    const float* pb = bsrc + (size_t)row * Csz;

    float v[4];
#pragma unroll
    for (int i = 0; i < 4; i++) {
        int c = tid + i * 256;
        v[i] = pa[c] + pb[c];
    }

    float s = v[0] + v[1] + v[2] + v[3];
    red[tid] = s;
    __syncthreads();
    for (int off = 128; off > 0; off >>= 1) {
        if (tid < off) red[tid] += red[tid + off];
        __syncthreads();
    }
    if (tid == 0) s_mu = red[0] * (1.0f / Csz);
    __syncthreads();
    const float mu = s_mu;

    float d2 = 0.0f;
#pragma unroll
    for (int i = 0; i < 4; i++) {
        float d = v[i] - mu;
        d2 = fmaf(d, d, d2);
    }
    __syncthreads();
    red[tid] = d2;
    __syncthreads();
    for (int off = 128; off > 0; off >>= 1) {
        if (tid < off) red[tid] += red[tid + off];
        __syncthreads();
    }
    if (tid == 0) s_rstd = rsqrtf(red[0] * (1.0f / Csz) + 1e-5f);
    __syncthreads();
    const float rstd = s_rstd;

#pragma unroll
    for (int i = 0; i < 4; i++) {
        int c = tid + i * 256;
        float o = (v[i] - mu) * rstd * g[c] + beta[c];
        out[(size_t)row * Csz + c] = o;
        if (oh16) oh16[(size_t)row * Csz + c] = __float2half(o);
    }
}

// ---------------------------------------------------------------------------
// Launch
// ---------------------------------------------------------------------------
extern "C" void kernel_launch(void* const* d_in, const int* in_sizes, int n_in,
                              void* d_out, int out_size)
{
    const float* x     = (const float*)d_in[0];
    const float* w_qkv = (const float*)d_in[1];
    const float* b_qkv = (const float*)d_in[2];
    const float* ln1_g = (const float*)d_in[3];
    const float* ln1_b = (const float*)d_in[4];
    const float* w_fc1 = (const float*)d_in[5];
    const float* b_fc1 = (const float*)d_in[6];
    const float* w_fc2 = (const float*)d_in[7];
    const float* b_fc2 = (const float*)d_in[8];
    const float* ln2_g = (const float*)d_in[9];
    const float* ln2_b = (const float*)d_in[10];
    float* out = (float*)d_out;

    float *attn, *x1, *mlp;
    __half *x16, *qkvh, *qkvl, *x1h16, *h16;
    __half *wqh, *wql, *w1h, *w2h;
    cudaGetSymbolAddress((void**)&attn, g_attn);
    cudaGetSymbolAddress((void**)&x1,   g_x1);
    cudaGetSymbolAddress((void**)&mlp,  g_mlp);
    cudaGetSymbolAddress((void**)&x16,  g_x_f16);
    cudaGetSymbolAddress((void**)&qkvh, g_qkv_h); cudaGetSymbolAddress((void**)&qkvl, g_qkv_l);
    cudaGetSymbolAddress((void**)&x1h16, g_x1_h16);
    cudaGetSymbolAddress((void**)&h16,   g_h_h16);
    cudaGetSymbolAddress((void**)&wqh, g_wqkv_h); cudaGetSymbolAddress((void**)&wql, g_wqkv_l);
    cudaGetSymbolAddress((void**)&w1h, g_wfc1_h);
    cudaGetSymbolAddress((void**)&w2h, g_wfc2_h);

    cudaFuncSetAttribute(fc_gemm<2, 2>, cudaFuncAttributeMaxDynamicSharedMemorySize, G_SMEM_MAX);
    cudaFuncSetAttribute(fc_gemm<1, 1>, cudaFuncAttributeMaxDynamicSharedMemorySize, G_SMEM_MAX);
    cudaFuncSetAttribute(fc_gemm<0, 1>, cudaFuncAttributeMaxDynamicSharedMemorySize, G_SMEM_MAX);
    cudaFuncSetAttribute(attn_mma_kernel, cudaFuncAttributeMaxDynamicSharedMemorySize, ATT_SMEM);

    // Prep: x -> fp16; transpose(+split) weights
    tofp16_kernel<<<(Msz * Csz / 4 + 255) / 256, 256>>>(x, x16, Msz * Csz / 4);
    wsplit_t_f16_kernel<<<dim3(3 * Csz / 32, Csz / 32), 256>>>(w_qkv, wqh, wql, Csz, 3 * Csz);
    wsplit_t_f16_kernel<<<dim3(4 * Csz / 32, Csz / 32), 256>>>(w_fc1, w1h, nullptr, Csz, 4 * Csz);
    wsplit_t_f16_kernel<<<dim3(Csz / 32, 4 * Csz / 32), 256>>>(w_fc2, w2h, nullptr, 4 * Csz, Csz);

    // 1. qkv = x @ Wqkv + b  (2-term) -> fp16 hi + lo
    fc_gemm<2, 2><<<dim3(3 * Csz / 128, Msz / 128), 256, 2 * 3 * GTILE_B>>>(
        x16, wqh, wql, b_qkv, nullptr, qkvh, qkvl, Msz, 3 * Csz, Csz);

    // 2. attention (fp16 2-term MMA)
    attn_mma_kernel<<<dim3(Tsz / 64, Hsz, Bsz), 128, ATT_SMEM>>>(qkvh, qkvl, attn);

    // 3. x1 = LN1(x + attn)  (+ fp16 emit)
    add_ln_kernel<<<Msz, 256>>>(x, attn, ln1_g, ln1_b, x1, x1h16);

    // 4. h = gelu(x1 @ W1 + b1)  (1-term) -> fp16
    fc_gemm<1, 1><<<dim3(4 * Csz / 128, Msz / 128), 256, 2 * 2 * GTILE_B>>>(
        x1h16, w1h, nullptr, b_fc1, nullptr, h16, nullptr, Msz, 4 * Csz, Csz);

    // 5. mlp = h @ W2 + b2  (1-term) -> fp32
    fc_gemm<0, 1><<<dim3(Csz / 128, Msz / 128), 256, 2 * 2 * GTILE_B>>>(
        h16, w2h, nullptr, b_fc2, mlp, nullptr, nullptr, Msz, Csz, 4 * Csz);

    // 6. out = LN2(x1 + mlp)
    add_ln_kernel<<<Msz, 256>>>(x1, mlp, ln2_g, ln2_b, out, nullptr);
}